// round 1
// baseline (speedup 1.0000x reference)
#include <cuda_runtime.h>
#include <cuda_bf16.h>

// Problem constants (match reference)
#define HH   720
#define WW   1280
#define CC   2
#define NPIX (CC * HH * WW)        // 1,843,200
#define TEVT 10
#define TTOT 20

// Persistent scratch (no cudaMalloc allowed)
__device__ float    g_buf[TEVT * NPIX];   // event count frames, ~73.7 MB
__device__ float    g_mem[NPIX];          // LIF membrane state, ~7.4 MB
__device__ int      g_counts[TTOT];       // spike counts per step
__device__ unsigned g_tmin_bits;          // t >= 0 -> float bits order as uint
__device__ unsigned g_tmax_bits;

// exp(-1/10) rounded to nearest f32 by the compiler
#define DECAY 0.9048374180359595f

// ---------------------------------------------------------------------------
// 1) Reset all state (graph replays must be deterministic)
// ---------------------------------------------------------------------------
__global__ void init_kernel() {
    const size_t total4 = (size_t)(TEVT * NPIX + NPIX) / 4;  // buf + mem, in float4
    const size_t nbuf4  = (size_t)TEVT * NPIX / 4;
    float4 z = make_float4(0.f, 0.f, 0.f, 0.f);
    float4* buf4 = reinterpret_cast<float4*>(g_buf);
    float4* mem4 = reinterpret_cast<float4*>(g_mem);
    size_t idx    = (size_t)blockIdx.x * blockDim.x + threadIdx.x;
    size_t stride = (size_t)gridDim.x * blockDim.x;
    for (size_t i = idx; i < total4; i += stride) {
        if (i < nbuf4) buf4[i] = z;
        else           mem4[i - nbuf4] = z;
    }
    if (idx == 0) {
        #pragma unroll
        for (int k = 0; k < TTOT; k++) g_counts[k] = 0;
        g_tmin_bits = 0x7F800000u;  // +inf
        g_tmax_bits = 0x00000000u;  // 0.0 (t uniform in [0,1), all >= 0)
    }
}

// ---------------------------------------------------------------------------
// 2) Exact min/max of t. t >= 0 so IEEE bits compare monotonically as uint.
// ---------------------------------------------------------------------------
__global__ void minmax_kernel(const float* __restrict__ t, int n) {
    float lmin = __int_as_float(0x7F800000);   // +inf
    float lmax = 0.0f;
    int idx    = blockIdx.x * blockDim.x + threadIdx.x;
    int stride = gridDim.x * blockDim.x;
    for (int i = idx; i < n; i += stride) {
        float v = t[i];
        lmin = fminf(lmin, v);
        lmax = fmaxf(lmax, v);
    }
    // warp reduce
    #pragma unroll
    for (int off = 16; off > 0; off >>= 1) {
        lmin = fminf(lmin, __shfl_xor_sync(0xFFFFFFFFu, lmin, off));
        lmax = fmaxf(lmax, __shfl_xor_sync(0xFFFFFFFFu, lmax, off));
    }
    __shared__ float smin[8], smax[8];
    int wid = threadIdx.x >> 5, lid = threadIdx.x & 31;
    if (lid == 0) { smin[wid] = lmin; smax[wid] = lmax; }
    __syncthreads();
    if (threadIdx.x == 0) {
        float bmin = smin[0], bmax = smax[0];
        int nw = blockDim.x >> 5;
        for (int w = 1; w < nw; w++) {
            bmin = fminf(bmin, smin[w]);
            bmax = fmaxf(bmax, smax[w]);
        }
        atomicMin(&g_tmin_bits, __float_as_uint(bmin));
        atomicMax(&g_tmax_bits, __float_as_uint(bmax));
    }
}

// ---------------------------------------------------------------------------
// 3) Scatter events into g_buf (atomic float add of 1.0 — exact for counts)
// ---------------------------------------------------------------------------
__global__ void scatter_kernel(const int* __restrict__ x, const int* __restrict__ y,
                               const int* __restrict__ p, const float* __restrict__ t,
                               int n) {
    int i = blockIdx.x * blockDim.x + threadIdx.x;
    if (i >= n) return;
    float tmin = __uint_as_float(g_tmin_bits);
    float tmax = __uint_as_float(g_tmax_bits);
    bool  gt   = tmax > tmin;
    float denom = gt ? (tmax - tmin) : 1.0f;
    float tn    = gt ? ((t[i] - tmin) / denom * (10.0f - 1e-6f)) : 0.0f;
    int ti = (int)tn;                       // trunc toward zero, tn >= 0
    ti = min(max(ti, 0), TEVT - 1);
    int xi = min(max(x[i], 0), WW - 1);
    int yi = min(max(y[i], 0), HH - 1);
    int c  = min(max(p[i], 0), CC - 1);
    atomicAdd(&g_buf[((ti * CC + c) * HH + yi) * WW + xi], 1.0f);
}

// ---------------------------------------------------------------------------
// 4) One LIF step. Every block recomputes thr_s from the finalized spike
//    counts of prior steps (cheap scalar recursion, avoids 20 extra kernels).
// ---------------------------------------------------------------------------
__global__ void __launch_bounds__(256) step_kernel(float* __restrict__ out, int s) {
    __shared__ float s_thr;
    __shared__ int   s_cnt;
    if (threadIdx.x == 0) {
        float thr = 1.0f;
        for (int k = 0; k < s; k++) {
            float rate = (float)g_counts[k] / (float)NPIX;
            thr = thr + 0.1f * (rate - 0.1f);
            thr = fminf(fmaxf(thr, 0.1f), 10.0f);
        }
        s_thr = thr;
        s_cnt = 0;
    }
    __syncthreads();
    const float thr = s_thr;

    float4*       mem4 = reinterpret_cast<float4*>(g_mem);
    const float4* buf4 = reinterpret_cast<const float4*>(g_buf + (size_t)s * NPIX);
    float4*       out4 = reinterpret_cast<float4*>(out + (size_t)s * NPIX);
    const int n4 = NPIX / 4;  // 460,800

    int cnt = 0;
    int idx    = blockIdx.x * blockDim.x + threadIdx.x;
    int stride = gridDim.x * blockDim.x;
    const bool has_frame = (s < TEVT);

    for (int i = idx; i < n4; i += stride) {
        float4 m = mem4[i];
        float4 f = has_frame ? buf4[i] : make_float4(0.f, 0.f, 0.f, 0.f);
        float4 o;
        m.x = m.x * DECAY + f.x;
        m.y = m.y * DECAY + f.y;
        m.z = m.z * DECAY + f.z;
        m.w = m.w * DECAY + f.w;
        bool sx = (m.x >= thr), sy = (m.y >= thr), sz = (m.z >= thr), sw = (m.w >= thr);
        if (sx) { m.x -= thr; cnt++; }
        if (sy) { m.y -= thr; cnt++; }
        if (sz) { m.z -= thr; cnt++; }
        if (sw) { m.w -= thr; cnt++; }
        o.x = sx ? 1.0f : 0.0f;
        o.y = sy ? 1.0f : 0.0f;
        o.z = sz ? 1.0f : 0.0f;
        o.w = sw ? 1.0f : 0.0f;
        mem4[i] = m;
        out4[i] = o;
    }

    // block reduce spike count -> one global atomic per block
    unsigned wsum = __reduce_add_sync(0xFFFFFFFFu, (unsigned)cnt);
    if ((threadIdx.x & 31) == 0) atomicAdd(&s_cnt, (int)wsum);
    __syncthreads();
    if (threadIdx.x == 0) atomicAdd(&g_counts[s], s_cnt);
}

// ---------------------------------------------------------------------------
// Launch: 23 graph nodes, all async, allocation-free.
// Inputs (metadata order): x:int32[4M], y:int32[4M], p:int32[4M], t:float32[4M]
// Output: float32[20*2*720*1280]
// ---------------------------------------------------------------------------
extern "C" void kernel_launch(void* const* d_in, const int* in_sizes, int n_in,
                              void* d_out, int out_size) {
    const int*   x = (const int*)d_in[0];
    const int*   y = (const int*)d_in[1];
    const int*   p = (const int*)d_in[2];
    const float* t = (const float*)d_in[3];
    float* out = (float*)d_out;
    int n = in_sizes[0];

    init_kernel<<<2048, 256>>>();
    minmax_kernel<<<1184, 256>>>(t, n);
    scatter_kernel<<<(n + 255) / 256, 256>>>(x, y, p, t, n);
    for (int s = 0; s < TTOT; s++) {
        step_kernel<<<1800, 256>>>(out, s);
    }
}

// round 4
// speedup vs baseline: 1.0872x; 1.0872x over previous
#include <cuda_runtime.h>
#include <cuda_bf16.h>

// Problem constants (match reference)
#define HH   720
#define WW   1280
#define CC   2
#define NPIX (CC * HH * WW)        // 1,843,200
#define N4   (NPIX / 4)            // 460,800 float4 per frame
#define TEVT 10
#define TTOT 20

// Conservative co-residency: 1 block per SM, 148 <= SM count on B300/GB300.
#define BLOCKS   148
#define TPB      512
#define NTHREADS (BLOCKS * TPB)    // 75,776
// per-thread items: j=0..5 full (6*75776 = 454,656 <= N4), j=6 partial:
#define NFULL    6
#define NPART    (N4 - NFULL * NTHREADS)   // 6,144 threads carry a 7th item

#define DECAY 0.9048374180359595f  // exp(-1/10) rounded to f32

// Persistent scratch (no cudaMalloc allowed)
__device__ float    g_buf[TEVT * NPIX];   // event count frames, ~73.7 MB
__device__ int      g_counts[TTOT];       // spike counts per step
__device__ float    g_bmin[BLOCKS];
__device__ float    g_bmax[BLOCKS];
__device__ unsigned g_barcnt = 0;         // barrier arrival counter
__device__ unsigned g_bargen = 0;         // barrier generation (monotonic forever)

// ---------------------------------------------------------------------------
// Device-wide sense-reversing barrier. Replay-safe: gen is monotonic across
// graph replays; count is reset by the last arriver BEFORE the gen bump.
// ---------------------------------------------------------------------------
__device__ __forceinline__ void grid_barrier() {
    __syncthreads();
    if (threadIdx.x == 0) {
        __threadfence();                                   // publish block's writes
        volatile unsigned* genp = &g_bargen;
        unsigned gen = *genp;                              // read BEFORE arriving
        unsigned v = atomicAdd(&g_barcnt, 1u);
        if (v == BLOCKS - 1) {
            atomicExch(&g_barcnt, 0u);                     // reset while others spin
            __threadfence();
            atomicAdd(&g_bargen, 1u);                      // release
        } else {
            while (*genp == gen) { __nanosleep(32); }
        }
        __threadfence();                                   // acquire others' writes
    }
    __syncthreads();
}

// ---------------------------------------------------------------------------
// One fused persistent kernel: init -> minmax -> scatter -> 20 LIF steps.
// Membrane state lives in registers (7 float4/thread) for the whole scan.
// ---------------------------------------------------------------------------
__global__ void __launch_bounds__(TPB, 1) fused_kernel(
    const int* __restrict__ x, const int* __restrict__ y,
    const int* __restrict__ p, const float* __restrict__ t,
    float* __restrict__ out, int n)
{
    const int tid = blockIdx.x * TPB + threadIdx.x;
    __shared__ float smin[TPB / 32], smax[TPB / 32];
    __shared__ float s_tmin, s_tmax;
    __shared__ int   s_cnt, s_tot;

    // ===== Phase 1: zero buf, block-local min/max of t, zero counts =====
    {
        float4 z = make_float4(0.f, 0.f, 0.f, 0.f);
        float4* buf4 = reinterpret_cast<float4*>(g_buf);
        const int nb4 = TEVT * N4;
        for (int i = tid; i < nb4; i += NTHREADS) buf4[i] = z;
    }
    {
        float lmin = __int_as_float(0x7F800000), lmax = 0.0f;  // t in [0,1)
        for (int i = tid; i < n; i += NTHREADS) {
            float v = __ldcs(&t[i]);
            lmin = fminf(lmin, v);
            lmax = fmaxf(lmax, v);
        }
        #pragma unroll
        for (int off = 16; off > 0; off >>= 1) {
            lmin = fminf(lmin, __shfl_xor_sync(0xFFFFFFFFu, lmin, off));
            lmax = fmaxf(lmax, __shfl_xor_sync(0xFFFFFFFFu, lmax, off));
        }
        if ((threadIdx.x & 31) == 0) { smin[threadIdx.x >> 5] = lmin; smax[threadIdx.x >> 5] = lmax; }
        __syncthreads();
        if (threadIdx.x == 0) {
            float bm = smin[0], bM = smax[0];
            #pragma unroll
            for (int w = 1; w < TPB / 32; w++) { bm = fminf(bm, smin[w]); bM = fmaxf(bM, smax[w]); }
            g_bmin[blockIdx.x] = bm;
            g_bmax[blockIdx.x] = bM;
            if (blockIdx.x == 0) {
                #pragma unroll
                for (int k = 0; k < TTOT; k++) g_counts[k] = 0;
            }
        }
    }
    grid_barrier();

    // ===== Phase 2: reduce global min/max, scatter events =====
    {
        float m = __int_as_float(0x7F800000), M = 0.0f;
        if (threadIdx.x < BLOCKS) { m = g_bmin[threadIdx.x]; M = g_bmax[threadIdx.x]; }
        #pragma unroll
        for (int off = 16; off > 0; off >>= 1) {
            m = fminf(m, __shfl_xor_sync(0xFFFFFFFFu, m, off));
            M = fmaxf(M, __shfl_xor_sync(0xFFFFFFFFu, M, off));
        }
        if ((threadIdx.x & 31) == 0) { smin[threadIdx.x >> 5] = m; smax[threadIdx.x >> 5] = M; }
        __syncthreads();
        if (threadIdx.x == 0) {
            float bm = smin[0], bM = smax[0];
            #pragma unroll
            for (int w = 1; w < TPB / 32; w++) { bm = fminf(bm, smin[w]); bM = fmaxf(bM, smax[w]); }
            s_tmin = bm; s_tmax = bM;
        }
        __syncthreads();
    }
    {
        const float tmin = s_tmin, tmax = s_tmax;
        const bool  gt   = tmax > tmin;
        const float denom = gt ? (tmax - tmin) : 1.0f;
        for (int i = tid; i < n; i += NTHREADS) {
            float tv = __ldcs(&t[i]);
            float tn = gt ? ((tv - tmin) / denom * (10.0f - 1e-6f)) : 0.0f;
            int ti = (int)tn;                        // trunc toward zero, tn >= 0
            ti = min(max(ti, 0), TEVT - 1);
            int xi = min(max(__ldcs(&x[i]), 0), WW - 1);
            int yi = min(max(__ldcs(&y[i]), 0), HH - 1);
            int c  = min(max(__ldcs(&p[i]), 0), CC - 1);
            atomicAdd(&g_buf[((ti * CC + c) * HH + yi) * WW + xi], 1.0f);
        }
    }
    grid_barrier();

    // ===== Phase 3: 20 LIF steps, membrane state in registers =====
    float4 mreg[NFULL + 1];
    #pragma unroll
    for (int j = 0; j <= NFULL; j++) mreg[j] = make_float4(0.f, 0.f, 0.f, 0.f);
    const bool aP = (tid < NPART);     // 7th item active for first 6144 threads
    float thr = 1.0f;                  // identical recursion in every thread

    for (int s = 0; s < TTOT; s++) {
        if (threadIdx.x == 0) s_cnt = 0;
        __syncthreads();

        const float4* f4 = reinterpret_cast<const float4*>(g_buf + (size_t)s * NPIX);
        float4*       o4 = reinterpret_cast<float4*>(out + (size_t)s * NPIX);
        const bool has_frame = (s < TEVT);
        int cnt = 0;

        #pragma unroll
        for (int j = 0; j <= NFULL; j++) {
            const int  idx    = tid + j * NTHREADS;
            const bool active = (j < NFULL) || aP;
            if (active) {
                float4 f = has_frame ? __ldcs(&f4[idx])
                                     : make_float4(0.f, 0.f, 0.f, 0.f);
                float4& m = mreg[j];
                m.x = m.x * DECAY + f.x;
                m.y = m.y * DECAY + f.y;
                m.z = m.z * DECAY + f.z;
                m.w = m.w * DECAY + f.w;
                bool sx = (m.x >= thr), sy = (m.y >= thr);
                bool sz = (m.z >= thr), sw = (m.w >= thr);
                if (sx) { m.x -= thr; cnt++; }
                if (sy) { m.y -= thr; cnt++; }
                if (sz) { m.z -= thr; cnt++; }
                if (sw) { m.w -= thr; cnt++; }
                float4 o = make_float4(sx ? 1.f : 0.f, sy ? 1.f : 0.f,
                                       sz ? 1.f : 0.f, sw ? 1.f : 0.f);
                __stcs(&o4[idx], o);
            }
        }

        // block-reduce spike count -> one global atomic per block
        unsigned wsum = __reduce_add_sync(0xFFFFFFFFu, (unsigned)cnt);
        if ((threadIdx.x & 31) == 0) atomicAdd(&s_cnt, (int)wsum);
        __syncthreads();
        if (threadIdx.x == 0) atomicAdd(&g_counts[s], s_cnt);

        grid_barrier();                 // publishes & orders g_counts[s]

        if (threadIdx.x == 0) s_tot = g_counts[s];
        __syncthreads();
        float rate = (float)s_tot / (float)NPIX;
        thr = thr + 0.1f * (rate - 0.1f);
        thr = fminf(fmaxf(thr, 0.1f), 10.0f);
    }
}

// ---------------------------------------------------------------------------
// Launch: ONE graph node, allocation-free, graph-capturable.
// Inputs (metadata order): x:int32[4M], y:int32[4M], p:int32[4M], t:float32[4M]
// Output: float32[20*2*720*1280]
// ---------------------------------------------------------------------------
extern "C" void kernel_launch(void* const* d_in, const int* in_sizes, int n_in,
                              void* d_out, int out_size) {
    const int*   x = (const int*)d_in[0];
    const int*   y = (const int*)d_in[1];
    const int*   p = (const int*)d_in[2];
    const float* t = (const float*)d_in[3];
    float* out = (float*)d_out;
    int n = in_sizes[0];

    fused_kernel<<<BLOCKS, TPB>>>(x, y, p, t, out, n);
}